// round 1
// baseline (speedup 1.0000x reference)
#include <cuda_runtime.h>

// Problem constants
#define Bn 8
#define Cn 256
#define Hn 96
#define Wn 128
#define Dd 4
#define NS 9      // 2*D+1
#define Qn 81     // NS*NS
#define HW (Hn*Wn)

// Tiling
#define TY 2                  // y rows per block
#define RX 4                  // x pixels per thread
#define XG (Wn/RX)            // 32 x-groups
#define NTHREADS (TY*XG*NS)   // 576
#define CC 16                 // channels per smem chunk
#define FBW (Wn + 2*Dd)       // 136 (halo row width)
#define FBH (TY + 2*Dd)       // 10  (halo rows)

#define SMEM_FA_FLOATS (CC*TY*Wn)     // 4096
#define SMEM_FB_FLOATS (CC*FBH*FBW)   // 21760
#define SMEM_BYTES ((SMEM_FA_FLOATS + SMEM_FB_FLOATS)*4)  // 103424

// Per-pixel inverse norms (scratch; no dynamic allocation allowed)
__device__ float g_inva[Bn*HW];
__device__ float g_invb[Bn*HW];

// ---------------------------------------------------------------------------
// Pass 1: per-pixel inverse L2 norms over the channel dim.
// grid (48, 8), 256 threads. Coalesced along x; 256 strided channel reads.
// ---------------------------------------------------------------------------
__global__ void norm_kernel(const float* __restrict__ fa,
                            const float* __restrict__ fb) {
    int pix = blockIdx.x * blockDim.x + threadIdx.x;   // 0..12287
    int b   = blockIdx.y;
    const float* pa = fa + (size_t)b * Cn * HW + pix;
    const float* pb = fb + (size_t)b * Cn * HW + pix;
    float sa = 0.f, sb = 0.f;
#pragma unroll 8
    for (int c = 0; c < Cn; c++) {
        float va = pa[(size_t)c * HW];
        float vb = pb[(size_t)c * HW];
        sa = fmaf(va, va, sa);
        sb = fmaf(vb, vb, sb);
    }
    g_inva[b * HW + pix] = 1.0f / fmaxf(sqrtf(sa), 1e-12f);
    g_invb[b * HW + pix] = 1.0f / fmaxf(sqrtf(sb), 1e-12f);
}

// ---------------------------------------------------------------------------
// Pass 2: correlation. Block = (b, 2-row y tile, full W).
// Thread = (yl, 4 x-pixels, one dy) -> 9 dx accumulators x 4 pixels = 36 acc.
// Per channel: 1x LDS.128 fa + 3x LDS.128 fb window + 36 FFMA.
// ---------------------------------------------------------------------------
__global__ void __launch_bounds__(NTHREADS, 1)
corr_kernel(const float* __restrict__ fa,
            const float* __restrict__ fb,
            float* __restrict__ out) {
    extern __shared__ float smem[];
    float* s_fa = smem;                      // [CC][TY*Wn]
    float* s_fb = smem + SMEM_FA_FLOATS;     // [CC][FBH][FBW]

    const int b   = blockIdx.y;
    const int y0  = blockIdx.x * TY;
    const int tid = threadIdx.x;

    const int dy = tid / (TY * XG);          // 0..8
    const int r  = tid % (TY * XG);
    const int yl = r / XG;                   // 0..1
    const int xg = r % XG;                   // 0..31
    const int x0 = xg * RX;

    const size_t baseA = (size_t)b * Cn * HW;

    // ---- loader role precompute (hoisted out of the channel loop) ----
    // fa: 64 float4 per channel (2 rows x 32 float4)
    const bool fa_role = (tid < TY * (Wn / 4));          // tid < 64
    int fa_gofs = 0, fa_sofs = 0;
    if (fa_role) {
        int yy  = tid / (Wn / 4);
        int xx4 = tid % (Wn / 4);
        fa_gofs = (y0 + yy) * Wn + xx4 * 4;
        fa_sofs = yy * Wn + xx4 * 4;
    }
    // fb: 10 rows x 34 float4 slots per channel; slots 0 and 33 are halo-zeros
    const bool fb_role = (tid < FBH * (FBW / 4));        // tid < 340
    int fb_gofs = 0, fb_sofs = 0;
    bool fb_valid = false;
    if (fb_role) {
        int hr = tid / (FBW / 4);
        int k  = tid % (FBW / 4);
        int yy = y0 - Dd + hr;
        fb_valid = (yy >= 0) && (yy < Hn) && (k >= 1) && (k <= Wn / 4);
        fb_gofs = yy * Wn + (k * 4 - 4);
        fb_sofs = hr * FBW + k * 4;
    }

    // zero-fill fb smem once (halo slots stay zero for the whole kernel)
    {
        float4 z = make_float4(0.f, 0.f, 0.f, 0.f);
        float4* p = (float4*)s_fb;
        for (int i = tid; i < SMEM_FB_FLOATS / 4; i += NTHREADS) p[i] = z;
    }

    float acc[NS][RX];
#pragma unroll
    for (int d = 0; d < NS; d++)
#pragma unroll
        for (int i = 0; i < RX; i++) acc[d][i] = 0.f;

    const int ofsA = yl * Wn + x0;
    const int ofsB = (yl + dy) * FBW + x0;

    for (int c0 = 0; c0 < Cn; c0 += CC) {
        __syncthreads();  // prev compute done (and zero-fill on first iter)
        // ---- load CC channels into smem ----
#pragma unroll 4
        for (int cc = 0; cc < CC; cc++) {
            const size_t cbase = baseA + (size_t)(c0 + cc) * HW;
            if (fa_role) {
                float4 v = *(const float4*)(fa + cbase + fa_gofs);
                *(float4*)(s_fa + cc * (TY * Wn) + fa_sofs) = v;
            }
            if (fb_role && fb_valid) {
                float4 v = *(const float4*)(fb + cbase + fb_gofs);
                *(float4*)(s_fb + cc * (FBH * FBW) + fb_sofs) = v;
            }
        }
        __syncthreads();
        // ---- compute ----
#pragma unroll 2
        for (int cc = 0; cc < CC; cc++) {
            const float* fap = s_fa + cc * (TY * Wn) + ofsA;
            const float* fbp = s_fb + cc * (FBH * FBW) + ofsB;
            float4 A  = *(const float4*)fap;
            float4 V0 = *(const float4*)(fbp);
            float4 V1 = *(const float4*)(fbp + 4);
            float4 V2 = *(const float4*)(fbp + 8);
            float a[RX] = {A.x, A.y, A.z, A.w};
            float v[RX + 2 * Dd] = {V0.x, V0.y, V0.z, V0.w,
                                    V1.x, V1.y, V1.z, V1.w,
                                    V2.x, V2.y, V2.z, V2.w};
#pragma unroll
            for (int dx = 0; dx < NS; dx++)
#pragma unroll
                for (int i = 0; i < RX; i++)
                    acc[dx][i] = fmaf(a[i], v[dx + i], acc[dx][i]);
        }
    }

    // ---- epilogue: scale by inverse norms, write float4 per dx ----
    const int y = y0 + yl;
    float ia[RX];
#pragma unroll
    for (int i = 0; i < RX; i++) ia[i] = g_inva[b * HW + y * Wn + x0 + i];

    const int sy = y + dy - Dd;
    const bool rowok = (unsigned)sy < (unsigned)Hn;
    float ib[RX + 2 * Dd];
#pragma unroll
    for (int k = 0; k < RX + 2 * Dd; k++) {
        int sx = x0 + k - Dd;
        ib[k] = (rowok && (unsigned)sx < (unsigned)Wn)
                    ? g_invb[b * HW + sy * Wn + sx] : 0.f;
        // raw acc is exactly 0 for OOB (zero-padded halo), so ib=0 is safe
    }

#pragma unroll
    for (int dx = 0; dx < NS; dx++) {
        float4 o;
        o.x = acc[dx][0] * ia[0] * ib[dx + 0];
        o.y = acc[dx][1] * ia[1] * ib[dx + 1];
        o.z = acc[dx][2] * ia[2] * ib[dx + 2];
        o.w = acc[dx][3] * ia[3] * ib[dx + 3];
        const int q = dy * NS + dx;
        *(float4*)(out + ((size_t)(b * Qn + q) * Hn + y) * Wn + x0) = o;
    }
}

// ---------------------------------------------------------------------------
extern "C" void kernel_launch(void* const* d_in, const int* in_sizes, int n_in,
                              void* d_out, int out_size) {
    const float* fa = (const float*)d_in[0];
    const float* fb = (const float*)d_in[1];
    float* out = (float*)d_out;

    norm_kernel<<<dim3(HW / 256, Bn), 256>>>(fa, fb);

    cudaFuncSetAttribute(corr_kernel,
                         cudaFuncAttributeMaxDynamicSharedMemorySize,
                         SMEM_BYTES);
    corr_kernel<<<dim3(Hn / TY, Bn), NTHREADS, SMEM_BYTES>>>(fa, fb, out);
}

// round 2
// speedup vs baseline: 1.6174x; 1.6174x over previous
#include <cuda_runtime.h>
#include <cstdint>

// Problem constants
#define Bn 8
#define Cn 256
#define Hn 96
#define Wn 128
#define Dd 4
#define NS 9      // 2*D+1
#define Qn 81     // NS*NS
#define HW (Hn*Wn)

// Tiling
#define TY 2                  // y rows per block
#define RX 4                  // x pixels per thread
#define XG (Wn/RX)            // 32 x-groups
#define NTHREADS (TY*XG*NS)   // 576
#define CC 16                 // channels per smem chunk
#define NCHUNK (Cn/CC)        // 16
#define FBW (Wn + 2*Dd)       // 136 (halo row width)
#define FBH (TY + 2*Dd)       // 10  (halo rows)

#define FA_FLOATS (CC*TY*Wn)          // 4096
#define FB_FLOATS (CC*FBH*FBW)        // 21760
#define STAGE_FLOATS (FA_FLOATS + FB_FLOATS)   // 25856
#define SMEM_BYTES (2*STAGE_FLOATS*4)          // 206848 (<= 227KB)

// Per-pixel inverse norms (scratch; no dynamic allocation allowed)
__device__ float g_inva[Bn*HW];
__device__ float g_invb[Bn*HW];

// ---------------------------------------------------------------------------
// Pass 1: per-pixel inverse L2 norms over the channel dim. (~30us, HBM-bound)
// ---------------------------------------------------------------------------
__global__ void norm_kernel(const float* __restrict__ fa,
                            const float* __restrict__ fb) {
    int pix = blockIdx.x * blockDim.x + threadIdx.x;
    int b   = blockIdx.y;
    const float* pa = fa + (size_t)b * Cn * HW + pix;
    const float* pb = fb + (size_t)b * Cn * HW + pix;
    float sa = 0.f, sb = 0.f;
#pragma unroll 8
    for (int c = 0; c < Cn; c++) {
        float va = pa[(size_t)c * HW];
        float vb = pb[(size_t)c * HW];
        sa = fmaf(va, va, sa);
        sb = fmaf(vb, vb, sb);
    }
    g_inva[b * HW + pix] = 1.0f / fmaxf(sqrtf(sa), 1e-12f);
    g_invb[b * HW + pix] = 1.0f / fmaxf(sqrtf(sb), 1e-12f);
}

// ---------------------------------------------------------------------------
// cp.async 16B helper: src-size as register enables zfill (src-size = 0)
// ---------------------------------------------------------------------------
__device__ __forceinline__ void cp16(uint32_t saddr, const float* g, int nbytes) {
    asm volatile("cp.async.cg.shared.global [%0], [%1], 16, %2;"
                 :: "r"(saddr), "l"(g), "r"(nbytes));
}

// ---------------------------------------------------------------------------
// Pass 2: correlation with a 2-stage cp.async pipeline.
// Block = (b, 2-row y tile, full W). Thread = (yl, 4 x-pixels, one dy).
// Per channel: 1x LDS.128 fa + 3x LDS.128 fb + 36 FFMA.
// Chunk c+1 is prefetched (LDGSTS) while chunk c is computed.
// ---------------------------------------------------------------------------
__global__ void __launch_bounds__(NTHREADS, 1)
corr_kernel(const float* __restrict__ fa,
            const float* __restrict__ fb,
            float* __restrict__ out) {
    extern __shared__ float smem[];

    const int b   = blockIdx.y;
    const int y0  = blockIdx.x * TY;
    const int tid = threadIdx.x;

    const int dy = tid / (TY * XG);          // 0..8
    const int r  = tid % (TY * XG);
    const int yl = r / XG;                   // 0..1
    const int xg = r % XG;                   // 0..31
    const int x0 = xg * RX;

    const size_t baseA = (size_t)b * Cn * HW;

    // ---- loader role precompute (hoisted out of the channel loop) ----
    // fa: 64 float4 slots per channel (2 rows x 32 float4)
    const bool fa_role = (tid < TY * (Wn / 4));          // tid < 64
    int fa_gofs = 0, fa_sofs = 0;
    if (fa_role) {
        int yy  = tid / (Wn / 4);
        int xx4 = tid % (Wn / 4);
        fa_gofs = (y0 + yy) * Wn + xx4 * 4;
        fa_sofs = yy * Wn + xx4 * 4;
    }
    // fb: 10 rows x 34 float4 slots per channel; invalid slots use zfill
    const bool fb_role = (tid < FBH * (FBW / 4));        // tid < 340
    int fb_gofs = 0, fb_sofs = 0, fb_bytes = 0;
    if (fb_role) {
        int hr = tid / (FBW / 4);
        int k  = tid % (FBW / 4);
        int yy = y0 - Dd + hr;
        bool valid = (yy >= 0) && (yy < Hn) && (k >= 1) && (k <= Wn / 4);
        fb_bytes = valid ? 16 : 0;
        int yyc = min(max(yy, 0), Hn - 1);      // clamped safe address
        int kc  = min(max(k, 1), Wn / 4);
        fb_gofs = yyc * Wn + (kc * 4 - 4);
        fb_sofs = hr * FBW + k * 4;
    }

    const uint32_t smem_u = (uint32_t)__cvta_generic_to_shared(smem);

    auto prefetch = [&](int c0, int st) {
        const uint32_t sbase = smem_u + (uint32_t)(st * STAGE_FLOATS * 4);
        const float* ga = fa + baseA + (size_t)c0 * HW;
        const float* gb = fb + baseA + (size_t)c0 * HW;
#pragma unroll
        for (int cc = 0; cc < CC; cc++) {
            if (fa_role)
                cp16(sbase + (uint32_t)((cc * (TY * Wn) + fa_sofs) * 4),
                     ga + (size_t)cc * HW + fa_gofs, 16);
            if (fb_role)
                cp16(sbase + (uint32_t)((FA_FLOATS + cc * (FBH * FBW) + fb_sofs) * 4),
                     gb + (size_t)cc * HW + fb_gofs, fb_bytes);
        }
    };

    float acc[NS][RX];
#pragma unroll
    for (int d = 0; d < NS; d++)
#pragma unroll
        for (int i = 0; i < RX; i++) acc[d][i] = 0.f;

    const int ofsA = yl * Wn + x0;
    const int ofsB = (yl + dy) * FBW + x0;

    // ---- pipeline prologue ----
    prefetch(0, 0);
    asm volatile("cp.async.commit_group;");

    int st = 0;
    for (int ch = 0; ch < NCHUNK; ch++) {
        asm volatile("cp.async.wait_group 0;");   // chunk ch landed
        __syncthreads();                          // visible to all; buf st^1 free
        if (ch + 1 < NCHUNK) prefetch((ch + 1) * CC, st ^ 1);
        asm volatile("cp.async.commit_group;");

        const float* s_fa = smem + st * STAGE_FLOATS;
        const float* s_fb = s_fa + FA_FLOATS;
#pragma unroll 2
        for (int cc = 0; cc < CC; cc++) {
            const float* fap = s_fa + cc * (TY * Wn) + ofsA;
            const float* fbp = s_fb + cc * (FBH * FBW) + ofsB;
            float4 A  = *(const float4*)fap;
            float4 V0 = *(const float4*)(fbp);
            float4 V1 = *(const float4*)(fbp + 4);
            float4 V2 = *(const float4*)(fbp + 8);
            float a[RX] = {A.x, A.y, A.z, A.w};
            float v[RX + 2 * Dd] = {V0.x, V0.y, V0.z, V0.w,
                                    V1.x, V1.y, V1.z, V1.w,
                                    V2.x, V2.y, V2.z, V2.w};
#pragma unroll
            for (int dx = 0; dx < NS; dx++)
#pragma unroll
                for (int i = 0; i < RX; i++)
                    acc[dx][i] = fmaf(a[i], v[dx + i], acc[dx][i]);
        }
        st ^= 1;
    }

    // ---- epilogue: scale by inverse norms, write float4 per dx ----
    const int y = y0 + yl;
    float ia[RX];
#pragma unroll
    for (int i = 0; i < RX; i++) ia[i] = g_inva[b * HW + y * Wn + x0 + i];

    const int sy = y + dy - Dd;
    const bool rowok = (unsigned)sy < (unsigned)Hn;
    float ib[RX + 2 * Dd];
#pragma unroll
    for (int k = 0; k < RX + 2 * Dd; k++) {
        int sx = x0 + k - Dd;
        ib[k] = (rowok && (unsigned)sx < (unsigned)Wn)
                    ? g_invb[b * HW + sy * Wn + sx] : 0.f;
        // raw acc is exactly 0 for OOB (zfill halo), so ib=0 is safe
    }

#pragma unroll
    for (int dx = 0; dx < NS; dx++) {
        float4 o;
        o.x = acc[dx][0] * ia[0] * ib[dx + 0];
        o.y = acc[dx][1] * ia[1] * ib[dx + 1];
        o.z = acc[dx][2] * ia[2] * ib[dx + 2];
        o.w = acc[dx][3] * ia[3] * ib[dx + 3];
        const int q = dy * NS + dx;
        *(float4*)(out + ((size_t)(b * Qn + q) * Hn + y) * Wn + x0) = o;
    }
}

// ---------------------------------------------------------------------------
extern "C" void kernel_launch(void* const* d_in, const int* in_sizes, int n_in,
                              void* d_out, int out_size) {
    const float* fa = (const float*)d_in[0];
    const float* fb = (const float*)d_in[1];
    float* out = (float*)d_out;

    norm_kernel<<<dim3(HW / 256, Bn), 256>>>(fa, fb);

    cudaFuncSetAttribute(corr_kernel,
                         cudaFuncAttributeMaxDynamicSharedMemorySize,
                         SMEM_BYTES);
    corr_kernel<<<dim3(Hn / TY, Bn), NTHREADS, SMEM_BYTES>>>(fa, fb, out);
}